// round 9
// baseline (speedup 1.0000x reference)
#include <cuda_runtime.h>
#include <math.h>

#define BATCH 8
#define NA    261888
#define KTOP  6000
#define PROP  1000
#define SHIFT 14
#define NBUCK (1 << 18)
#define CAP   8192
#define SORTN 8192

#define MASKW32 192          /* u32 words per mask row (= 96 u64, 6144 bits) */
#define MASKW64 96

/* ---------------- device scratch (static: no allocation allowed) -------- */
__device__ unsigned int       g_hist[BATCH][NBUCK];
__device__ unsigned int       g_maxbucket[BATCH];
__device__ int                g_thresh[BATCH];
__device__ unsigned int       g_total[BATCH];
__device__ unsigned long long g_cand[BATCH][CAP];
__device__ float4             g_boxes[BATCH * KTOP];
__device__ float              g_areas[BATCH * KTOP];
__device__ unsigned int       g_mask[BATCH][KTOP][MASKW32];   /* ~37 MB */

/* order-preserving float -> uint key */
__device__ __forceinline__ unsigned int fkey(float s) {
    unsigned int u = __float_as_uint(s);
    return u ^ ((unsigned int)((int)u >> 31) | 0x80000000u);
}

/* ---------------- kernel 0: clear scratch ------------------------------ */
__global__ void clear_kernel() {
    size_t tid    = (size_t)blockIdx.x * blockDim.x + threadIdx.x;
    size_t stride = (size_t)gridDim.x * blockDim.x;
    uint4* h4 = (uint4*)&g_hist[0][0];
    size_t n4 = (size_t)BATCH * NBUCK / 4;
    uint4 z4 = make_uint4(0, 0, 0, 0);
    for (size_t i = tid; i < n4; i += stride) h4[i] = z4;
    unsigned long long* c = &g_cand[0][0];
    for (size_t i = tid; i < (size_t)BATCH * CAP; i += stride) c[i] = 0ull;
    if (tid < BATCH) g_maxbucket[tid] = 0u;
}

/* ---------------- kernel 1: per-batch bucket histogram ------------------ */
__global__ void hist_kernel(const float* __restrict__ probs) {
    int b = blockIdx.y;
    const float* p = probs + (size_t)b * NA * 2;
    unsigned int lmax = 0;
    for (int a = blockIdx.x * blockDim.x + threadIdx.x; a < NA;
         a += gridDim.x * blockDim.x) {
        unsigned int key = fkey(p[2 * a + 1]);
        unsigned int bk = key >> SHIFT;
        atomicAdd(&g_hist[b][bk], 1u);
        lmax = max(lmax, bk);
    }
    __shared__ unsigned int sm[256];
    sm[threadIdx.x] = lmax;
    __syncthreads();
    for (int o = 128; o > 0; o >>= 1) {
        if (threadIdx.x < o) sm[threadIdx.x] = max(sm[threadIdx.x], sm[threadIdx.x + o]);
        __syncthreads();
    }
    if (threadIdx.x == 0) atomicMax(&g_maxbucket[b], sm[0]);
}

/* ---------------- kernel 2: find threshold bucket, write fill bases ----- */
__global__ void findthresh_kernel() {
    int b = blockIdx.x, tid = threadIdx.x;
    __shared__ unsigned int scnt[256];
    __shared__ unsigned int s_running;
    if (tid == 0) s_running = 0;
    __syncthreads();
    int start = (int)g_maxbucket[b];
    for (int cs = start; cs >= 0; cs -= 256) {
        int bk = cs - tid;
        unsigned int c = (bk >= 0) ? g_hist[b][bk] : 0u;
        scnt[tid] = c;
        __syncthreads();
        for (int off = 1; off < 256; off <<= 1) {
            unsigned int v = (tid >= off) ? scnt[tid - off] : 0u;
            __syncthreads();
            scnt[tid] += v;
            __syncthreads();
        }
        unsigned int incl = scnt[tid];
        unsigned int excl = incl - c;
        unsigned int run = s_running;
        if (bk >= 0 && run + excl < KTOP) {
            g_hist[b][bk] = run + excl;
            if (run + incl >= KTOP) {
                g_thresh[b] = bk;
                g_total[b]  = run + incl;
            }
        }
        __syncthreads();
        if (tid == 0) s_running = run + scnt[255];
        __syncthreads();
        if (s_running >= KTOP) break;
    }
}

/* ---------------- kernel 3: compact candidates (grouped by bucket) ------ */
__global__ void compact_kernel(const float* __restrict__ probs) {
    int b = blockIdx.y;
    int tb = g_thresh[b];
    const float* p = probs + (size_t)b * NA * 2;
    for (int a = blockIdx.x * blockDim.x + threadIdx.x; a < NA;
         a += gridDim.x * blockDim.x) {
        unsigned int key = fkey(p[2 * a + 1]);
        unsigned int bk = key >> SHIFT;
        if ((int)bk >= tb) {
            unsigned int pos = atomicAdd(&g_hist[b][bk], 1u);
            if (pos < CAP)
                g_cand[b][pos] =
                    ((unsigned long long)key << 32) | (unsigned int)(~a);
        }
    }
}

/* ---------------- kernel 4: bitonic sort + gather + box decode ---------- */
__global__ void __launch_bounds__(1024, 1)
sort_gather_kernel(const float* __restrict__ bbox,
                   const float* __restrict__ anchors) {
    extern __shared__ unsigned long long s[];
    int b = blockIdx.x, tid = threadIdx.x;
    for (int i = tid; i < SORTN; i += blockDim.x) s[i] = g_cand[b][i];
    __syncthreads();
    for (int k = 2; k <= SORTN; k <<= 1) {
        for (int j = k >> 1; j > 0; j >>= 1) {
            for (int i = tid; i < SORTN; i += blockDim.x) {
                int ixj = i ^ j;
                if (ixj > i) {
                    unsigned long long x = s[i], y = s[ixj];
                    bool up = ((i & k) == 0);
                    if (up ? (x < y) : (x > y)) { s[i] = y; s[ixj] = x; }
                }
            }
            __syncthreads();
        }
    }
    const float4* anc = (const float4*)(anchors + (size_t)b * NA * 4);
    const float4* dl  = (const float4*)(bbox    + (size_t)b * NA * 4);
    for (int i = tid; i < KTOP; i += blockDim.x) {
        unsigned int idx = ~(unsigned int)(s[i]);
        float4 a4 = anc[idx];
        float4 r4 = dl[idx];
        float d0 = __fmul_rn(r4.x, 0.1f);
        float d1 = __fmul_rn(r4.y, 0.1f);
        float d2 = __fmul_rn(r4.z, 0.2f);
        float d3 = __fmul_rn(r4.w, 0.2f);
        float h  = __fsub_rn(a4.z, a4.x);
        float w  = __fsub_rn(a4.w, a4.y);
        float cy = __fadd_rn(__fadd_rn(a4.x, __fmul_rn(0.5f, h)), __fmul_rn(d0, h));
        float cx = __fadd_rn(__fadd_rn(a4.y, __fmul_rn(0.5f, w)), __fmul_rn(d1, w));
        float h2 = __fmul_rn(h, expf(d2));
        float w2 = __fmul_rn(w, expf(d3));
        float y1 = __fsub_rn(cy, __fmul_rn(0.5f, h2));
        float x1 = __fsub_rn(cx, __fmul_rn(0.5f, w2));
        float y2 = __fadd_rn(y1, h2);
        float x2 = __fadd_rn(x1, w2);
        y1 = fminf(fmaxf(y1, 0.0f), 1.0f);
        x1 = fminf(fmaxf(x1, 0.0f), 1.0f);
        y2 = fminf(fmaxf(y2, 0.0f), 1.0f);
        x2 = fminf(fmaxf(x2, 0.0f), 1.0f);
        g_boxes[b * KTOP + i] = make_float4(y1, x1, y2, x2);
        g_areas[b * KTOP + i] = __fmul_rn(__fsub_rn(y2, y1), __fsub_rn(x2, x1));
    }
}

/* ------- kernel 5: suppression-mask build (warp-per-row, lane-per-j) ---- */
/* EXACT copy of the round-4 version (proven 725us config).                 */
#define MBK_THREADS 256
#define MBK_ROWS    32        /* rows per block (8 warps x 4 rows) */
#define MBK_CHUNK   2048

__global__ void __launch_bounds__(MBK_THREADS)
mask_build_kernel() {
    int b       = blockIdx.y;
    int rowbase = blockIdx.x * MBK_ROWS;
    int warp    = threadIdx.x >> 5;
    int lane    = threadIdx.x & 31;

    __shared__ float4 sbox[MBK_CHUNK];
    __shared__ float  sarea[MBK_CHUNK];

    const float4* boxes = g_boxes + b * KTOP;
    const float*  areas = g_areas + b * KTOP;

    for (int chunk = 0; chunk < KTOP; chunk += MBK_CHUNK) {
        int cn = min(MBK_CHUNK, KTOP - chunk);
        __syncthreads();
        for (int t = threadIdx.x; t < cn; t += MBK_THREADS) {
            sbox[t]  = boxes[chunk + t];
            sarea[t] = areas[chunk + t];
        }
        __syncthreads();
        if (chunk + cn <= rowbase) continue;
#pragma unroll
        for (int r = 0; r < 4; ++r) {
            int i = rowbase + warp * 4 + r;          /* warp-uniform row */
            if (i >= KTOP) break;
            float4 rb = boxes[i];                    /* broadcast load   */
            float  ra = areas[i];
            int wstart = (i > chunk) ? ((i - chunk) >> 5) : 0;
            int wend   = (cn + 31) >> 5;
            for (int wd = wstart; wd < wend; ++wd) {
                int j = chunk + wd * 32 + lane;
                bool sup = false;
                if (j < KTOP) {
                    float4 cbx = sbox[wd * 32 + lane];
                    float  cax = sarea[wd * 32 + lane];
                    float yy1 = fmaxf(rb.x, cbx.x);
                    float xx1 = fmaxf(rb.y, cbx.y);
                    float yy2 = fminf(rb.z, cbx.z);
                    float xx2 = fminf(rb.w, cbx.w);
                    float inter = __fmul_rn(fmaxf(__fsub_rn(yy2, yy1), 0.0f),
                                            fmaxf(__fsub_rn(xx2, xx1), 0.0f));
                    if (inter > 0.0f) {
                        float uni = __fsub_rn(__fadd_rn(ra, cax), inter);
                        if (uni > 0.0f)
                            sup = !(__fdiv_rn(inter, uni) <= 0.7f);
                    }
                }
                unsigned int word = __ballot_sync(0xFFFFFFFFu, sup);
                if (lane == 0)
                    g_mask[b][i][(chunk >> 5) + wd] = word;
            }
        }
    }
}

/* ------- kernel 6: serial greedy pass (4-wide, lane0 scan, owner bytes) - */
#define NC 4

__global__ void __launch_bounds__(32, 1)
nms_serial_kernel(float* __restrict__ out) {
    int b    = blockIdx.x;
    int lane = threadIdx.x;
    __shared__ unsigned long long sV[96];
    __shared__ int s_picks[PROP];
    __shared__ int s_cand[NC];
    __shared__ unsigned int s_sup[NC];
    __shared__ int s_ctl[4];          /* ncand, acc, step, fill */

    /* valid bitmap in registers + smem mirror.
       u64 word wu = g*32 + lane covers bits [wu*64, wu*64+63].             */
    unsigned long long V[3];
#pragma unroll
    for (int g = 0; g < 3; ++g) {
        int wu = g * 32 + lane;
        V[g] = (wu < 93) ? ~0ull
             : (wu == 93) ? ((1ull << 48) - 1ull) : 0ull;
        sV[wu] = V[g];
    }
    __syncwarp();

    const unsigned long long* mask64 =
        (const unsigned long long*)&g_mask[b][0][0];

    int step = 0, fill = -1;
    int cursor = 0;                   /* lane 0 only; monotone */

    while (true) {
        /* ---- phase 1: lane 0 scalar-scans smem for first <=NC set bits - */
        if (lane == 0) {
            int found = 0, cur = cursor;
            while (found < NC) {
                int wu = cur >> 6;
                if (wu >= 94) break;
                unsigned long long w = sV[wu] & (~0ull << (cur & 63));
                while (w && found < NC) {
                    int bx = __ffsll((long long)w) - 1;
                    s_cand[found++] = (wu << 6) + bx;
                    w &= w - 1ull;
                }
                cur = (wu + 1) << 6;
            }
            s_ctl[0] = found;
            cursor = (found == NC) ? (s_cand[NC - 1] + 1) : 6016;
        }
        __syncwarp();
        int ncand = s_ctl[0];
        if (ncand == 0) break;        /* exhausted -> zeros remain */

        /* ---- phase 2: parallel load of candidate mask rows ---- */
        int cnd[NC];
        unsigned long long m[NC][3];
#pragma unroll
        for (int t = 0; t < NC; ++t) {
            if (t < ncand) {
                cnd[t] = s_cand[t];
                const unsigned long long* row = mask64 + (size_t)cnd[t] * MASKW64;
                m[t][0] = row[lane];
                m[t][1] = row[lane + 32];
                m[t][2] = row[lane + 64];
            } else {
                cnd[t] = -1;
                m[t][0] = m[t][1] = m[t][2] = 0ull;
            }
        }

        /* ---- phase 3: owner lanes build suppressed-by bytes (no shfl) -- */
#pragma unroll
        for (int t = 0; t < NC; ++t) {
            if (t < ncand) {
                int c = cnd[t];
                int wdi = c >> 6;
                if ((wdi & 31) == lane) {
                    int g = wdi >> 5, bidx = c & 63;
                    unsigned int byte = 0;
#pragma unroll
                    for (int s = 0; s < NC; ++s) {
                        unsigned long long w =
                            (g == 0) ? m[s][0] : (g == 1) ? m[s][1] : m[s][2];
                        byte |= (unsigned int)((w >> bidx) & 1ull) << s;
                    }
                    s_sup[t] = byte;
                }
            }
        }
        __syncwarp();

        /* ---- phase 4: lane 0 resolves greedy acceptance ---- */
        if (lane == 0) {
            int acc = 0, sp = step, fl = -1;
            for (int t = 0; t < ncand && sp < PROP; ++t) {
                unsigned int sb = s_sup[t];
                if ((sb & (unsigned int)acc) == 0u) {
                    acc |= 1 << t;
                    s_picks[sp++] = s_cand[t];
                    if (((sb >> t) & 1u) == 0u) {    /* degenerate box */
                        fl = s_cand[t];
                        break;
                    }
                }
            }
            s_ctl[1] = acc; s_ctl[2] = sp; s_ctl[3] = fl;
        }
        __syncwarp();
        int acc = s_ctl[1];
        step = s_ctl[2];
        fill = s_ctl[3];

        /* ---- phase 5: apply accepted masks, refresh smem mirror ---- */
#pragma unroll
        for (int t = 0; t < NC; ++t) {
            if (acc & (1 << t)) {
                V[0] &= ~m[t][0]; V[1] &= ~m[t][1]; V[2] &= ~m[t][2];
            }
        }
        sV[lane] = V[0]; sV[lane + 32] = V[1]; sV[lane + 64] = V[2];
        __syncwarp();

        if (fill >= 0 || step >= PROP) break;
    }

    /* ---- fill remainder + output gather ---- */
    for (int s2 = step + lane; s2 < PROP; s2 += 32) s_picks[s2] = fill;
    __syncwarp();
    const float4* boxes = g_boxes + b * KTOP;
    float4* o = (float4*)out + b * PROP;
    for (int s2 = lane; s2 < PROP; s2 += 32) {
        int p = s_picks[s2];
        o[s2] = (p >= 0) ? boxes[p] : make_float4(0.f, 0.f, 0.f, 0.f);
    }
}

/* ---------------- launch ------------------------------------------------ */
extern "C" void kernel_launch(void* const* d_in, const int* in_sizes, int n_in,
                              void* d_out, int out_size) {
    const float* probs   = (const float*)d_in[0];  /* (B, A, 2) */
    const float* bbox    = (const float*)d_in[1];  /* (B, A, 4) */
    const float* anchors = (const float*)d_in[2];  /* (B, A, 4) */
    float* out = (float*)d_out;                    /* (B, 1000, 4) */

    cudaFuncSetAttribute(sort_gather_kernel,
                         cudaFuncAttributeMaxDynamicSharedMemorySize, SORTN * 8);

    clear_kernel<<<1024, 256>>>();
    dim3 hg(256, BATCH);
    hist_kernel<<<hg, 256>>>(probs);
    findthresh_kernel<<<BATCH, 256>>>();
    compact_kernel<<<hg, 256>>>(probs);
    sort_gather_kernel<<<BATCH, 1024, SORTN * 8>>>(bbox, anchors);
    dim3 mg((KTOP + MBK_ROWS - 1) / MBK_ROWS, BATCH);
    mask_build_kernel<<<mg, MBK_THREADS>>>();
    nms_serial_kernel<<<BATCH, 32>>>(out);
}

// round 10
// speedup vs baseline: 1.2974x; 1.2974x over previous
#include <cuda_runtime.h>
#include <math.h>

#define BATCH 8
#define NA    261888
#define KTOP  6000
#define PROP  1000
#define SHIFT 14
#define NBUCK (1 << 18)
#define CAP   8192
#define SORTN 8192

#define SLOTS    32
#define SPILLCAP 32768

/* ---------------- device scratch (static: no allocation allowed) -------- */
__device__ unsigned int       g_hist[BATCH][NBUCK];
__device__ unsigned int       g_maxbucket[BATCH];
__device__ int                g_thresh[BATCH];
__device__ unsigned int       g_total[BATCH];
__device__ unsigned long long g_cand[BATCH][CAP];
__device__ float4             g_boxes[BATCH * KTOP];
__device__ float              g_areas[BATCH * KTOP];
__device__ unsigned int       g_pcnt[BATCH][KTOP];           /* pairs per row */
__device__ unsigned int       g_padj[BATCH][KTOP][SLOTS];    /* adjacency     */
__device__ unsigned int       g_spill[BATCH][SPILLCAP];      /* (i<<16)|j     */
__device__ unsigned int       g_spillcnt[BATCH];

/* order-preserving float -> uint key */
__device__ __forceinline__ unsigned int fkey(float s) {
    unsigned int u = __float_as_uint(s);
    return u ^ ((unsigned int)((int)u >> 31) | 0x80000000u);
}

/* ---------------- kernel 0: clear scratch ------------------------------ */
__global__ void clear_kernel() {
    size_t tid    = (size_t)blockIdx.x * blockDim.x + threadIdx.x;
    size_t stride = (size_t)gridDim.x * blockDim.x;
    uint4* h4 = (uint4*)&g_hist[0][0];
    size_t n4 = (size_t)BATCH * NBUCK / 4;
    uint4 z4 = make_uint4(0, 0, 0, 0);
    for (size_t i = tid; i < n4; i += stride) h4[i] = z4;
    unsigned long long* c = &g_cand[0][0];
    for (size_t i = tid; i < (size_t)BATCH * CAP; i += stride) c[i] = 0ull;
    unsigned int* pc = &g_pcnt[0][0];
    for (size_t i = tid; i < (size_t)BATCH * KTOP; i += stride) pc[i] = 0u;
    if (tid < BATCH) { g_maxbucket[tid] = 0u; g_spillcnt[tid] = 0u; }
}

/* ---------------- kernel 1: per-batch bucket histogram ------------------ */
__global__ void hist_kernel(const float* __restrict__ probs) {
    int b = blockIdx.y;
    const float* p = probs + (size_t)b * NA * 2;
    unsigned int lmax = 0;
    for (int a = blockIdx.x * blockDim.x + threadIdx.x; a < NA;
         a += gridDim.x * blockDim.x) {
        unsigned int key = fkey(p[2 * a + 1]);
        unsigned int bk = key >> SHIFT;
        atomicAdd(&g_hist[b][bk], 1u);
        lmax = max(lmax, bk);
    }
    __shared__ unsigned int sm[256];
    sm[threadIdx.x] = lmax;
    __syncthreads();
    for (int o = 128; o > 0; o >>= 1) {
        if (threadIdx.x < o) sm[threadIdx.x] = max(sm[threadIdx.x], sm[threadIdx.x + o]);
        __syncthreads();
    }
    if (threadIdx.x == 0) atomicMax(&g_maxbucket[b], sm[0]);
}

/* ---------------- kernel 2: find threshold bucket, write fill bases ----- */
__global__ void findthresh_kernel() {
    int b = blockIdx.x, tid = threadIdx.x;
    __shared__ unsigned int scnt[256];
    __shared__ unsigned int s_running;
    if (tid == 0) s_running = 0;
    __syncthreads();
    int start = (int)g_maxbucket[b];
    for (int cs = start; cs >= 0; cs -= 256) {
        int bk = cs - tid;
        unsigned int c = (bk >= 0) ? g_hist[b][bk] : 0u;
        scnt[tid] = c;
        __syncthreads();
        for (int off = 1; off < 256; off <<= 1) {
            unsigned int v = (tid >= off) ? scnt[tid - off] : 0u;
            __syncthreads();
            scnt[tid] += v;
            __syncthreads();
        }
        unsigned int incl = scnt[tid];
        unsigned int excl = incl - c;
        unsigned int run = s_running;
        if (bk >= 0 && run + excl < KTOP) {
            g_hist[b][bk] = run + excl;
            if (run + incl >= KTOP) {
                g_thresh[b] = bk;
                g_total[b]  = run + incl;
            }
        }
        __syncthreads();
        if (tid == 0) s_running = run + scnt[255];
        __syncthreads();
        if (s_running >= KTOP) break;
    }
}

/* ---------------- kernel 3: compact candidates (grouped by bucket) ------ */
__global__ void compact_kernel(const float* __restrict__ probs) {
    int b = blockIdx.y;
    int tb = g_thresh[b];
    const float* p = probs + (size_t)b * NA * 2;
    for (int a = blockIdx.x * blockDim.x + threadIdx.x; a < NA;
         a += gridDim.x * blockDim.x) {
        unsigned int key = fkey(p[2 * a + 1]);
        unsigned int bk = key >> SHIFT;
        if ((int)bk >= tb) {
            unsigned int pos = atomicAdd(&g_hist[b][bk], 1u);
            if (pos < CAP)
                g_cand[b][pos] =
                    ((unsigned long long)key << 32) | (unsigned int)(~a);
        }
    }
}

/* ---------------- kernel 4: bitonic sort + gather + box decode ---------- */
__global__ void __launch_bounds__(1024, 1)
sort_gather_kernel(const float* __restrict__ bbox,
                   const float* __restrict__ anchors) {
    extern __shared__ unsigned long long s[];
    int b = blockIdx.x, tid = threadIdx.x;
    for (int i = tid; i < SORTN; i += blockDim.x) s[i] = g_cand[b][i];
    __syncthreads();
    for (int k = 2; k <= SORTN; k <<= 1) {
        for (int j = k >> 1; j > 0; j >>= 1) {
            for (int i = tid; i < SORTN; i += blockDim.x) {
                int ixj = i ^ j;
                if (ixj > i) {
                    unsigned long long x = s[i], y = s[ixj];
                    bool up = ((i & k) == 0);
                    if (up ? (x < y) : (x > y)) { s[i] = y; s[ixj] = x; }
                }
            }
            __syncthreads();
        }
    }
    const float4* anc = (const float4*)(anchors + (size_t)b * NA * 4);
    const float4* dl  = (const float4*)(bbox    + (size_t)b * NA * 4);
    for (int i = tid; i < KTOP; i += blockDim.x) {
        unsigned int idx = ~(unsigned int)(s[i]);
        float4 a4 = anc[idx];
        float4 r4 = dl[idx];
        float d0 = __fmul_rn(r4.x, 0.1f);
        float d1 = __fmul_rn(r4.y, 0.1f);
        float d2 = __fmul_rn(r4.z, 0.2f);
        float d3 = __fmul_rn(r4.w, 0.2f);
        float h  = __fsub_rn(a4.z, a4.x);
        float w  = __fsub_rn(a4.w, a4.y);
        float cy = __fadd_rn(__fadd_rn(a4.x, __fmul_rn(0.5f, h)), __fmul_rn(d0, h));
        float cx = __fadd_rn(__fadd_rn(a4.y, __fmul_rn(0.5f, w)), __fmul_rn(d1, w));
        float h2 = __fmul_rn(h, expf(d2));
        float w2 = __fmul_rn(w, expf(d3));
        float y1 = __fsub_rn(cy, __fmul_rn(0.5f, h2));
        float x1 = __fsub_rn(cx, __fmul_rn(0.5f, w2));
        float y2 = __fadd_rn(y1, h2);
        float x2 = __fadd_rn(x1, w2);
        y1 = fminf(fmaxf(y1, 0.0f), 1.0f);
        x1 = fminf(fmaxf(x1, 0.0f), 1.0f);
        y2 = fminf(fmaxf(y2, 0.0f), 1.0f);
        x2 = fminf(fmaxf(x2, 0.0f), 1.0f);
        g_boxes[b * KTOP + i] = make_float4(y1, x1, y2, x2);
        g_areas[b * KTOP + i] = __fmul_rn(__fsub_rn(y2, y1), __fsub_rn(x2, x1));
    }
}

/* ------- kernel 5: sparse suppression-pair build ------------------------ */
/* Same loop structure + FP semantics as the proven mask_build; emits only  */
/* sparse pairs (i,j), j>i, IoU>0.7 instead of a dense bitmask.             */
#define MBK_THREADS 256
#define MBK_ROWS    32        /* rows per block (8 warps x 4 rows) */
#define MBK_CHUNK   2048

__global__ void __launch_bounds__(MBK_THREADS)
pair_build_kernel() {
    int b       = blockIdx.y;
    int rowbase = blockIdx.x * MBK_ROWS;
    int warp    = threadIdx.x >> 5;
    int lane    = threadIdx.x & 31;

    __shared__ float4 sbox[MBK_CHUNK];
    __shared__ float  sarea[MBK_CHUNK];

    const float4* boxes = g_boxes + b * KTOP;
    const float*  areas = g_areas + b * KTOP;

    for (int chunk = 0; chunk < KTOP; chunk += MBK_CHUNK) {
        int cn = min(MBK_CHUNK, KTOP - chunk);
        __syncthreads();
        for (int t = threadIdx.x; t < cn; t += MBK_THREADS) {
            sbox[t]  = boxes[chunk + t];
            sarea[t] = areas[chunk + t];
        }
        __syncthreads();
        if (chunk + cn <= rowbase) continue;
#pragma unroll
        for (int r = 0; r < 4; ++r) {
            int i = rowbase + warp * 4 + r;          /* warp-uniform row */
            if (i >= KTOP) break;
            float4 rb = boxes[i];                    /* broadcast load   */
            float  ra = areas[i];
            int wstart = (i + 1 > chunk) ? ((i + 1 - chunk) >> 5) : 0;
            int wend   = (cn + 31) >> 5;
            for (int wd = wstart; wd < wend; ++wd) {
                int j = chunk + wd * 32 + lane;
                bool sup = false;
                if (j > i && j < KTOP) {
                    float4 cbx = sbox[wd * 32 + lane];
                    float  cax = sarea[wd * 32 + lane];
                    float yy1 = fmaxf(rb.x, cbx.x);
                    float xx1 = fmaxf(rb.y, cbx.y);
                    float yy2 = fminf(rb.z, cbx.z);
                    float xx2 = fminf(rb.w, cbx.w);
                    float inter = __fmul_rn(fmaxf(__fsub_rn(yy2, yy1), 0.0f),
                                            fmaxf(__fsub_rn(xx2, xx1), 0.0f));
                    if (inter > 0.0f) {
                        float uni = __fsub_rn(__fadd_rn(ra, cax), inter);
                        if (uni > 0.0f)
                            sup = !(__fdiv_rn(inter, uni) <= 0.7f);
                    }
                }
                /* warp-uniform guard keeps the common (all-false) path cheap */
                if (__any_sync(0xFFFFFFFFu, sup)) {
                    if (sup) {
                        unsigned int pos = atomicAdd(&g_pcnt[b][i], 1u);
                        if (pos < SLOTS) {
                            g_padj[b][i][pos] = (unsigned int)j;
                        } else {
                            unsigned int sp2 = atomicAdd(&g_spillcnt[b], 1u);
                            if (sp2 < SPILLCAP)
                                g_spill[b][sp2] =
                                    ((unsigned int)i << 16) | (unsigned int)j;
                        }
                    }
                }
            }
        }
    }
}

/* ------- kernel 6: sparse serial greedy pass ---------------------------- */
__global__ void __launch_bounds__(32, 1)
nms_serial_kernel(float* __restrict__ out) {
    int b    = blockIdx.x;
    int lane = threadIdx.x;
    __shared__ unsigned long long sbm[94];     /* valid bitmap             */
    __shared__ unsigned long long szero[94];   /* zero-area flags          */
    __shared__ unsigned char      scnt[KTOP];  /* per-row pair count (cap) */
    __shared__ int                s_picks[PROP];
    __shared__ int                s_ctl[2];    /* step, fill */

    const float* areas = g_areas + b * KTOP;

    /* bitmap init: words 0..92 full, 93 has 48 bits */
    for (int wu = lane; wu < 94; wu += 32)
        sbm[wu] = (wu < 93) ? ~0ull : ((1ull << 48) - 1ull);

    /* zero-area flag bitmap via ballots */
    for (int wu = 0; wu < 94; ++wu) {
        int i1 = wu * 64 + lane;
        int i2 = i1 + 32;
        bool z1 = (i1 < KTOP) && (areas[i1] == 0.0f);
        bool z2 = (i2 < KTOP) && (areas[i2] == 0.0f);
        unsigned int lo = __ballot_sync(0xFFFFFFFFu, z1);
        unsigned int hi = __ballot_sync(0xFFFFFFFFu, z2);
        if (lane == 0)
            szero[wu] = ((unsigned long long)hi << 32) | lo;
    }

    /* pair counts -> smem bytes (clamped) */
    for (int i = lane; i < KTOP; i += 32) {
        unsigned int c = g_pcnt[b][i];
        scnt[i] = (unsigned char)(c > 255u ? 255u : c);
    }
    __syncwarp();

    if (lane == 0) {
        int cur = 0, sp = 0, fill = -1;
        int sc = (int)g_spillcnt[b];
        if (sc > SPILLCAP) sc = SPILLCAP;
        while (sp < PROP) {
            /* next set bit at/after cur (monotone cursor) */
            int wu = cur >> 6;
            unsigned long long w =
                (wu < 94) ? (sbm[wu] & (~0ull << (cur & 63))) : 0ull;
            while (!w) {
                if (++wu >= 94) break;
                w = sbm[wu];
            }
            if (wu >= 94) break;                  /* exhausted -> zeros */
            int i = (wu << 6) + (__ffsll((long long)w) - 1);
            s_picks[sp++] = i;
            if ((szero[wu] >> (i & 63)) & 1ull) { /* degenerate: repeats */
                fill = i;
                break;
            }
            cur = i + 1;
            int n = scnt[i];
            if (n) {
                const unsigned int* adj = g_padj[b][i];
                int mslots = n < SLOTS ? n : SLOTS;
                for (int t = 0; t < mslots; ++t) {
                    int j = (int)adj[t];
                    sbm[j >> 6] &= ~(1ull << (j & 63));
                }
                if (n > SLOTS) {                  /* rare overflow path */
                    for (int k = 0; k < sc; ++k) {
                        unsigned int p = g_spill[b][k];
                        if ((int)(p >> 16) == i) {
                            int j = (int)(p & 0xFFFFu);
                            sbm[j >> 6] &= ~(1ull << (j & 63));
                        }
                    }
                }
            }
        }
        s_ctl[0] = sp;
        s_ctl[1] = fill;
    }
    __syncwarp();
    int step = s_ctl[0];
    int fill = s_ctl[1];

    /* fill remainder + output gather */
    for (int s2 = step + lane; s2 < PROP; s2 += 32) s_picks[s2] = fill;
    __syncwarp();
    const float4* boxes = g_boxes + b * KTOP;
    float4* o = (float4*)out + b * PROP;
    for (int s2 = lane; s2 < PROP; s2 += 32) {
        int p = s_picks[s2];
        o[s2] = (p >= 0) ? boxes[p] : make_float4(0.f, 0.f, 0.f, 0.f);
    }
}

/* ---------------- launch ------------------------------------------------ */
extern "C" void kernel_launch(void* const* d_in, const int* in_sizes, int n_in,
                              void* d_out, int out_size) {
    const float* probs   = (const float*)d_in[0];  /* (B, A, 2) */
    const float* bbox    = (const float*)d_in[1];  /* (B, A, 4) */
    const float* anchors = (const float*)d_in[2];  /* (B, A, 4) */
    float* out = (float*)d_out;                    /* (B, 1000, 4) */

    cudaFuncSetAttribute(sort_gather_kernel,
                         cudaFuncAttributeMaxDynamicSharedMemorySize, SORTN * 8);

    clear_kernel<<<1024, 256>>>();
    dim3 hg(256, BATCH);
    hist_kernel<<<hg, 256>>>(probs);
    findthresh_kernel<<<BATCH, 256>>>();
    compact_kernel<<<hg, 256>>>(probs);
    sort_gather_kernel<<<BATCH, 1024, SORTN * 8>>>(bbox, anchors);
    dim3 mg((KTOP + MBK_ROWS - 1) / MBK_ROWS, BATCH);
    pair_build_kernel<<<mg, MBK_THREADS>>>();
    nms_serial_kernel<<<BATCH, 32>>>(out);
}

// round 11
// speedup vs baseline: 1.4641x; 1.1285x over previous
#include <cuda_runtime.h>
#include <math.h>

#define BATCH 8
#define NA    261888
#define KTOP  6000
#define PROP  1000
#define SHIFT 14
#define NBUCK (1 << 18)
#define CAP   8192
#define SORTN 8192

#define SLOTS    32
#define SPILLCAP 32768

/* ---------------- device scratch (static: no allocation allowed) -------- */
__device__ unsigned int       g_hist[BATCH][NBUCK];
__device__ unsigned int       g_maxbucket[BATCH];
__device__ int                g_thresh[BATCH];
__device__ unsigned int       g_total[BATCH];
__device__ unsigned long long g_cand[BATCH][CAP];
__device__ float4             g_boxes[BATCH * KTOP];
__device__ float              g_areas[BATCH * KTOP];
__device__ unsigned int       g_pcnt[BATCH][KTOP];           /* pairs per row */
__device__ unsigned int       g_padj[BATCH][KTOP][SLOTS];    /* adjacency     */
__device__ unsigned int       g_spill[BATCH][SPILLCAP];      /* (i<<16)|j     */
__device__ unsigned int       g_spillcnt[BATCH];

/* order-preserving float -> uint key */
__device__ __forceinline__ unsigned int fkey(float s) {
    unsigned int u = __float_as_uint(s);
    return u ^ ((unsigned int)((int)u >> 31) | 0x80000000u);
}

/* ---------------- kernel 0: clear scratch ------------------------------ */
__global__ void clear_kernel() {
    size_t tid    = (size_t)blockIdx.x * blockDim.x + threadIdx.x;
    size_t stride = (size_t)gridDim.x * blockDim.x;
    uint4* h4 = (uint4*)&g_hist[0][0];
    size_t n4 = (size_t)BATCH * NBUCK / 4;
    uint4 z4 = make_uint4(0, 0, 0, 0);
    for (size_t i = tid; i < n4; i += stride) h4[i] = z4;
    unsigned long long* c = &g_cand[0][0];
    for (size_t i = tid; i < (size_t)BATCH * CAP; i += stride) c[i] = 0ull;
    unsigned int* pc = &g_pcnt[0][0];
    for (size_t i = tid; i < (size_t)BATCH * KTOP; i += stride) pc[i] = 0u;
    if (tid < BATCH) { g_maxbucket[tid] = 0u; g_spillcnt[tid] = 0u; }
}

/* ---------------- kernel 1: per-batch bucket histogram ------------------ */
__global__ void hist_kernel(const float* __restrict__ probs) {
    int b = blockIdx.y;
    const float* p = probs + (size_t)b * NA * 2;
    unsigned int lmax = 0;
    for (int a = blockIdx.x * blockDim.x + threadIdx.x; a < NA;
         a += gridDim.x * blockDim.x) {
        unsigned int key = fkey(p[2 * a + 1]);
        unsigned int bk = key >> SHIFT;
        atomicAdd(&g_hist[b][bk], 1u);
        lmax = max(lmax, bk);
    }
    __shared__ unsigned int sm[256];
    sm[threadIdx.x] = lmax;
    __syncthreads();
    for (int o = 128; o > 0; o >>= 1) {
        if (threadIdx.x < o) sm[threadIdx.x] = max(sm[threadIdx.x], sm[threadIdx.x + o]);
        __syncthreads();
    }
    if (threadIdx.x == 0) atomicMax(&g_maxbucket[b], sm[0]);
}

/* ---------------- kernel 2: find threshold bucket, write fill bases ----- */
__global__ void findthresh_kernel() {
    int b = blockIdx.x, tid = threadIdx.x;
    __shared__ unsigned int scnt[256];
    __shared__ unsigned int s_running;
    if (tid == 0) s_running = 0;
    __syncthreads();
    int start = (int)g_maxbucket[b];
    for (int cs = start; cs >= 0; cs -= 256) {
        int bk = cs - tid;
        unsigned int c = (bk >= 0) ? g_hist[b][bk] : 0u;
        scnt[tid] = c;
        __syncthreads();
        for (int off = 1; off < 256; off <<= 1) {
            unsigned int v = (tid >= off) ? scnt[tid - off] : 0u;
            __syncthreads();
            scnt[tid] += v;
            __syncthreads();
        }
        unsigned int incl = scnt[tid];
        unsigned int excl = incl - c;
        unsigned int run = s_running;
        if (bk >= 0 && run + excl < KTOP) {
            g_hist[b][bk] = run + excl;
            if (run + incl >= KTOP) {
                g_thresh[b] = bk;
                g_total[b]  = run + incl;
            }
        }
        __syncthreads();
        if (tid == 0) s_running = run + scnt[255];
        __syncthreads();
        if (s_running >= KTOP) break;
    }
}

/* ---------------- kernel 3: compact candidates (grouped by bucket) ------ */
__global__ void compact_kernel(const float* __restrict__ probs) {
    int b = blockIdx.y;
    int tb = g_thresh[b];
    const float* p = probs + (size_t)b * NA * 2;
    for (int a = blockIdx.x * blockDim.x + threadIdx.x; a < NA;
         a += gridDim.x * blockDim.x) {
        unsigned int key = fkey(p[2 * a + 1]);
        unsigned int bk = key >> SHIFT;
        if ((int)bk >= tb) {
            unsigned int pos = atomicAdd(&g_hist[b][bk], 1u);
            if (pos < CAP)
                g_cand[b][pos] =
                    ((unsigned long long)key << 32) | (unsigned int)(~a);
        }
    }
}

/* ---------------- kernel 4: bitonic sort + gather + box decode ---------- */
__global__ void __launch_bounds__(1024, 1)
sort_gather_kernel(const float* __restrict__ bbox,
                   const float* __restrict__ anchors) {
    extern __shared__ unsigned long long s[];
    int b = blockIdx.x, tid = threadIdx.x;
    for (int i = tid; i < SORTN; i += blockDim.x) s[i] = g_cand[b][i];
    __syncthreads();
    for (int k = 2; k <= SORTN; k <<= 1) {
        for (int j = k >> 1; j > 0; j >>= 1) {
            for (int i = tid; i < SORTN; i += blockDim.x) {
                int ixj = i ^ j;
                if (ixj > i) {
                    unsigned long long x = s[i], y = s[ixj];
                    bool up = ((i & k) == 0);
                    if (up ? (x < y) : (x > y)) { s[i] = y; s[ixj] = x; }
                }
            }
            __syncthreads();
        }
    }
    const float4* anc = (const float4*)(anchors + (size_t)b * NA * 4);
    const float4* dl  = (const float4*)(bbox    + (size_t)b * NA * 4);
    for (int i = tid; i < KTOP; i += blockDim.x) {
        unsigned int idx = ~(unsigned int)(s[i]);
        float4 a4 = anc[idx];
        float4 r4 = dl[idx];
        float d0 = __fmul_rn(r4.x, 0.1f);
        float d1 = __fmul_rn(r4.y, 0.1f);
        float d2 = __fmul_rn(r4.z, 0.2f);
        float d3 = __fmul_rn(r4.w, 0.2f);
        float h  = __fsub_rn(a4.z, a4.x);
        float w  = __fsub_rn(a4.w, a4.y);
        float cy = __fadd_rn(__fadd_rn(a4.x, __fmul_rn(0.5f, h)), __fmul_rn(d0, h));
        float cx = __fadd_rn(__fadd_rn(a4.y, __fmul_rn(0.5f, w)), __fmul_rn(d1, w));
        float h2 = __fmul_rn(h, expf(d2));
        float w2 = __fmul_rn(w, expf(d3));
        float y1 = __fsub_rn(cy, __fmul_rn(0.5f, h2));
        float x1 = __fsub_rn(cx, __fmul_rn(0.5f, w2));
        float y2 = __fadd_rn(y1, h2);
        float x2 = __fadd_rn(x1, w2);
        y1 = fminf(fmaxf(y1, 0.0f), 1.0f);
        x1 = fminf(fmaxf(x1, 0.0f), 1.0f);
        y2 = fminf(fmaxf(y2, 0.0f), 1.0f);
        x2 = fminf(fmaxf(x2, 0.0f), 1.0f);
        g_boxes[b * KTOP + i] = make_float4(y1, x1, y2, x2);
        g_areas[b * KTOP + i] = __fmul_rn(__fsub_rn(y2, y1), __fsub_rn(x2, x1));
    }
}

/* ------- kernel 5: sparse pair build (wd-outer, 8 rows in registers) ---- */
#define MBK_THREADS 256
#define MBK_RPW     8                  /* rows per warp */
#define MBK_ROWS    (8 * MBK_RPW)      /* 64 rows per block */
#define MBK_CHUNK   2048

__global__ void __launch_bounds__(MBK_THREADS)
pair_build_kernel() {
    int b       = blockIdx.y;
    int rowbase = blockIdx.x * MBK_ROWS;
    int warp    = threadIdx.x >> 5;
    int lane    = threadIdx.x & 31;
    int i0      = rowbase + warp * MBK_RPW;   /* warp's first row */

    __shared__ float4 sbox[MBK_CHUNK];

    const float4* boxes = g_boxes + b * KTOP;
    const float*  areas = g_areas + b * KTOP;

    /* row boxes + areas in registers */
    float4 rb[MBK_RPW]; float ra[MBK_RPW];
#pragma unroll
    for (int r = 0; r < MBK_RPW; ++r) {
        int i = i0 + r;
        if (i < KTOP) { rb[r] = boxes[i]; ra[r] = areas[i]; }
        else { rb[r] = make_float4(0.f, 0.f, 0.f, 0.f); ra[r] = 0.f; }
    }

    for (int chunk = 0; chunk < KTOP; chunk += MBK_CHUNK) {
        int cn = min(MBK_CHUNK, KTOP - chunk);
        __syncthreads();
        for (int t = threadIdx.x; t < cn; t += MBK_THREADS)
            sbox[t] = boxes[chunk + t];
        __syncthreads();
        if (chunk + cn <= rowbase) continue;     /* no j > i in this chunk */

        /* first word that can contain j > i0 (warp-uniform) */
        int wstart = (i0 + 1 > chunk) ? ((i0 + 1 - chunk) >> 5) : 0;
        int wend   = (cn + 31) >> 5;
        for (int wd = wstart; wd < wend; ++wd) {
            int j = chunk + wd * 32 + lane;
            float4 cbx = sbox[wd * 32 + lane];
            /* area recomputed in-register: bit-identical to g_areas[j]
               (same __f*_rn expression on identical inputs)             */
            float cax = __fmul_rn(__fsub_rn(cbx.z, cbx.x),
                                  __fsub_rn(cbx.w, cbx.y));
            bool jok = (j < KTOP);
            unsigned int supmask = 0;            /* bit r: row i0+r suppresses j */
#pragma unroll
            for (int r = 0; r < MBK_RPW; ++r) {
                float yy1 = fmaxf(rb[r].x, cbx.x);
                float xx1 = fmaxf(rb[r].y, cbx.y);
                float yy2 = fminf(rb[r].z, cbx.z);
                float xx2 = fminf(rb[r].w, cbx.w);
                float inter = __fmul_rn(fmaxf(__fsub_rn(yy2, yy1), 0.0f),
                                        fmaxf(__fsub_rn(xx2, xx1), 0.0f));
                bool sup = false;
                if (inter > 0.0f && jok && j > i0 + r) {
                    float uni = __fsub_rn(__fadd_rn(ra[r], cax), inter);
                    if (uni > 0.0f)
                        sup = !(__fdiv_rn(inter, uni) <= 0.7f);
                }
                supmask |= sup ? (1u << r) : 0u;
            }
            /* warp-uniform guard: common path (no pair anywhere) is cheap */
            if (__any_sync(0xFFFFFFFFu, supmask != 0u)) {
                while (supmask) {
                    int r = __ffs(supmask) - 1;
                    supmask &= supmask - 1u;
                    int i = i0 + r;
                    unsigned int pos = atomicAdd(&g_pcnt[b][i], 1u);
                    if (pos < SLOTS) {
                        g_padj[b][i][pos] = (unsigned int)j;
                    } else {
                        unsigned int sp2 = atomicAdd(&g_spillcnt[b], 1u);
                        if (sp2 < SPILLCAP)
                            g_spill[b][sp2] =
                                ((unsigned int)i << 16) | (unsigned int)j;
                    }
                }
            }
        }
    }
}

/* ------- kernel 6: sparse serial greedy pass ---------------------------- */
__global__ void __launch_bounds__(32, 1)
nms_serial_kernel(float* __restrict__ out) {
    int b    = blockIdx.x;
    int lane = threadIdx.x;
    __shared__ unsigned long long sbm[94];     /* valid bitmap             */
    __shared__ unsigned long long szero[94];   /* zero-area flags          */
    __shared__ unsigned char      scnt[KTOP];  /* per-row pair count (cap) */
    __shared__ int                s_picks[PROP];
    __shared__ int                s_ctl[2];    /* step, fill */

    const float* areas = g_areas + b * KTOP;

    /* bitmap init: words 0..92 full, 93 has 48 bits */
    for (int wu = lane; wu < 94; wu += 32)
        sbm[wu] = (wu < 93) ? ~0ull : ((1ull << 48) - 1ull);

    /* zero-area flag bitmap via ballots */
    for (int wu = 0; wu < 94; ++wu) {
        int i1 = wu * 64 + lane;
        int i2 = i1 + 32;
        bool z1 = (i1 < KTOP) && (areas[i1] == 0.0f);
        bool z2 = (i2 < KTOP) && (areas[i2] == 0.0f);
        unsigned int lo = __ballot_sync(0xFFFFFFFFu, z1);
        unsigned int hi = __ballot_sync(0xFFFFFFFFu, z2);
        if (lane == 0)
            szero[wu] = ((unsigned long long)hi << 32) | lo;
    }

    /* pair counts -> smem bytes (clamped) */
    for (int i = lane; i < KTOP; i += 32) {
        unsigned int c = g_pcnt[b][i];
        scnt[i] = (unsigned char)(c > 255u ? 255u : c);
    }
    __syncwarp();

    if (lane == 0) {
        int cur = 0, sp = 0, fill = -1;
        int sc = (int)g_spillcnt[b];
        if (sc > SPILLCAP) sc = SPILLCAP;
        while (sp < PROP) {
            /* next set bit at/after cur (monotone cursor) */
            int wu = cur >> 6;
            unsigned long long w =
                (wu < 94) ? (sbm[wu] & (~0ull << (cur & 63))) : 0ull;
            while (!w) {
                if (++wu >= 94) break;
                w = sbm[wu];
            }
            if (wu >= 94) break;                  /* exhausted -> zeros */
            int i = (wu << 6) + (__ffsll((long long)w) - 1);
            s_picks[sp++] = i;
            if ((szero[wu] >> (i & 63)) & 1ull) { /* degenerate: repeats */
                fill = i;
                break;
            }
            cur = i + 1;
            int n = scnt[i];
            if (n) {
                const unsigned int* adj = g_padj[b][i];
                int mslots = n < SLOTS ? n : SLOTS;
                for (int t = 0; t < mslots; ++t) {
                    int j = (int)adj[t];
                    sbm[j >> 6] &= ~(1ull << (j & 63));
                }
                if (n > SLOTS) {                  /* rare overflow path */
                    for (int k = 0; k < sc; ++k) {
                        unsigned int p = g_spill[b][k];
                        if ((int)(p >> 16) == i) {
                            int j = (int)(p & 0xFFFFu);
                            sbm[j >> 6] &= ~(1ull << (j & 63));
                        }
                    }
                }
            }
        }
        s_ctl[0] = sp;
        s_ctl[1] = fill;
    }
    __syncwarp();
    int step = s_ctl[0];
    int fill = s_ctl[1];

    /* fill remainder + output gather */
    for (int s2 = step + lane; s2 < PROP; s2 += 32) s_picks[s2] = fill;
    __syncwarp();
    const float4* boxes = g_boxes + b * KTOP;
    float4* o = (float4*)out + b * PROP;
    for (int s2 = lane; s2 < PROP; s2 += 32) {
        int p = s_picks[s2];
        o[s2] = (p >= 0) ? boxes[p] : make_float4(0.f, 0.f, 0.f, 0.f);
    }
}

/* ---------------- launch ------------------------------------------------ */
extern "C" void kernel_launch(void* const* d_in, const int* in_sizes, int n_in,
                              void* d_out, int out_size) {
    const float* probs   = (const float*)d_in[0];  /* (B, A, 2) */
    const float* bbox    = (const float*)d_in[1];  /* (B, A, 4) */
    const float* anchors = (const float*)d_in[2];  /* (B, A, 4) */
    float* out = (float*)d_out;                    /* (B, 1000, 4) */

    cudaFuncSetAttribute(sort_gather_kernel,
                         cudaFuncAttributeMaxDynamicSharedMemorySize, SORTN * 8);

    clear_kernel<<<1024, 256>>>();
    dim3 hg(256, BATCH);
    hist_kernel<<<hg, 256>>>(probs);
    findthresh_kernel<<<BATCH, 256>>>();
    compact_kernel<<<hg, 256>>>(probs);
    sort_gather_kernel<<<BATCH, 1024, SORTN * 8>>>(bbox, anchors);
    dim3 mg((KTOP + MBK_ROWS - 1) / MBK_ROWS, BATCH);
    pair_build_kernel<<<mg, MBK_THREADS>>>();
    nms_serial_kernel<<<BATCH, 32>>>(out);
}

// round 12
// speedup vs baseline: 1.9734x; 1.3478x over previous
#include <cuda_runtime.h>
#include <math.h>

#define BATCH 8
#define NA    261888
#define KTOP  6000
#define PROP  1000
#define SHIFT 14
#define NBUCK (1 << 18)
#define CAP   8192
#define SORTN 8192

#define SLOTS    32
#define SPILLCAP 32768

#define CELLG    16
#define NCELL    (CELLG * CELLG)
#define CELLCAP  768

/* ---------------- device scratch (static: no allocation allowed) -------- */
__device__ unsigned int       g_hist[BATCH][NBUCK];
__device__ unsigned int       g_maxbucket[BATCH];
__device__ int                g_thresh[BATCH];
__device__ unsigned int       g_total[BATCH];
__device__ unsigned long long g_cand[BATCH][CAP];
__device__ float4             g_boxes[BATCH * KTOP];
__device__ float              g_areas[BATCH * KTOP];
__device__ unsigned int       g_pcnt[BATCH][KTOP];           /* pairs per row */
__device__ unsigned int       g_padj[BATCH][KTOP][SLOTS];    /* adjacency     */
__device__ unsigned int       g_spill[BATCH][SPILLCAP];      /* (i<<16)|j     */
__device__ unsigned int       g_spillcnt[BATCH];
__device__ unsigned int       g_ccnt[BATCH][NCELL];          /* boxes / cell  */
__device__ unsigned int       g_cells[BATCH][NCELL][CELLCAP];
__device__ unsigned int       g_cellovf[BATCH];              /* overflow flag */

/* order-preserving float -> uint key */
__device__ __forceinline__ unsigned int fkey(float s) {
    unsigned int u = __float_as_uint(s);
    return u ^ ((unsigned int)((int)u >> 31) | 0x80000000u);
}

/* ---------------- kernel 0: clear scratch ------------------------------ */
__global__ void clear_kernel() {
    size_t tid    = (size_t)blockIdx.x * blockDim.x + threadIdx.x;
    size_t stride = (size_t)gridDim.x * blockDim.x;
    uint4* h4 = (uint4*)&g_hist[0][0];
    size_t n4 = (size_t)BATCH * NBUCK / 4;
    uint4 z4 = make_uint4(0, 0, 0, 0);
    for (size_t i = tid; i < n4; i += stride) h4[i] = z4;
    unsigned long long* c = &g_cand[0][0];
    for (size_t i = tid; i < (size_t)BATCH * CAP; i += stride) c[i] = 0ull;
    unsigned int* pc = &g_pcnt[0][0];
    for (size_t i = tid; i < (size_t)BATCH * KTOP; i += stride) pc[i] = 0u;
    unsigned int* cc = &g_ccnt[0][0];
    for (size_t i = tid; i < (size_t)BATCH * NCELL; i += stride) cc[i] = 0u;
    if (tid < BATCH) {
        g_maxbucket[tid] = 0u; g_spillcnt[tid] = 0u; g_cellovf[tid] = 0u;
    }
}

/* ---------------- kernel 1: per-batch bucket histogram ------------------ */
__global__ void hist_kernel(const float* __restrict__ probs) {
    int b = blockIdx.y;
    const float* p = probs + (size_t)b * NA * 2;
    unsigned int lmax = 0;
    for (int a = blockIdx.x * blockDim.x + threadIdx.x; a < NA;
         a += gridDim.x * blockDim.x) {
        unsigned int key = fkey(p[2 * a + 1]);
        unsigned int bk = key >> SHIFT;
        atomicAdd(&g_hist[b][bk], 1u);
        lmax = max(lmax, bk);
    }
    __shared__ unsigned int sm[256];
    sm[threadIdx.x] = lmax;
    __syncthreads();
    for (int o = 128; o > 0; o >>= 1) {
        if (threadIdx.x < o) sm[threadIdx.x] = max(sm[threadIdx.x], sm[threadIdx.x + o]);
        __syncthreads();
    }
    if (threadIdx.x == 0) atomicMax(&g_maxbucket[b], sm[0]);
}

/* ---------------- kernel 2: find threshold bucket, write fill bases ----- */
__global__ void findthresh_kernel() {
    int b = blockIdx.x, tid = threadIdx.x;
    __shared__ unsigned int scnt[256];
    __shared__ unsigned int s_running;
    if (tid == 0) s_running = 0;
    __syncthreads();
    int start = (int)g_maxbucket[b];
    for (int cs = start; cs >= 0; cs -= 256) {
        int bk = cs - tid;
        unsigned int c = (bk >= 0) ? g_hist[b][bk] : 0u;
        scnt[tid] = c;
        __syncthreads();
        for (int off = 1; off < 256; off <<= 1) {
            unsigned int v = (tid >= off) ? scnt[tid - off] : 0u;
            __syncthreads();
            scnt[tid] += v;
            __syncthreads();
        }
        unsigned int incl = scnt[tid];
        unsigned int excl = incl - c;
        unsigned int run = s_running;
        if (bk >= 0 && run + excl < KTOP) {
            g_hist[b][bk] = run + excl;
            if (run + incl >= KTOP) {
                g_thresh[b] = bk;
                g_total[b]  = run + incl;
            }
        }
        __syncthreads();
        if (tid == 0) s_running = run + scnt[255];
        __syncthreads();
        if (s_running >= KTOP) break;
    }
}

/* ---------------- kernel 3: compact candidates (grouped by bucket) ------ */
__global__ void compact_kernel(const float* __restrict__ probs) {
    int b = blockIdx.y;
    int tb = g_thresh[b];
    const float* p = probs + (size_t)b * NA * 2;
    for (int a = blockIdx.x * blockDim.x + threadIdx.x; a < NA;
         a += gridDim.x * blockDim.x) {
        unsigned int key = fkey(p[2 * a + 1]);
        unsigned int bk = key >> SHIFT;
        if ((int)bk >= tb) {
            unsigned int pos = atomicAdd(&g_hist[b][bk], 1u);
            if (pos < CAP)
                g_cand[b][pos] =
                    ((unsigned long long)key << 32) | (unsigned int)(~a);
        }
    }
}

/* ---------------- kernel 4: bitonic sort + gather + box decode ---------- */
__global__ void __launch_bounds__(1024, 1)
sort_gather_kernel(const float* __restrict__ bbox,
                   const float* __restrict__ anchors) {
    extern __shared__ unsigned long long s[];
    int b = blockIdx.x, tid = threadIdx.x;
    for (int i = tid; i < SORTN; i += blockDim.x) s[i] = g_cand[b][i];
    __syncthreads();
    for (int k = 2; k <= SORTN; k <<= 1) {
        for (int j = k >> 1; j > 0; j >>= 1) {
            for (int i = tid; i < SORTN; i += blockDim.x) {
                int ixj = i ^ j;
                if (ixj > i) {
                    unsigned long long x = s[i], y = s[ixj];
                    bool up = ((i & k) == 0);
                    if (up ? (x < y) : (x > y)) { s[i] = y; s[ixj] = x; }
                }
            }
            __syncthreads();
        }
    }
    const float4* anc = (const float4*)(anchors + (size_t)b * NA * 4);
    const float4* dl  = (const float4*)(bbox    + (size_t)b * NA * 4);
    for (int i = tid; i < KTOP; i += blockDim.x) {
        unsigned int idx = ~(unsigned int)(s[i]);
        float4 a4 = anc[idx];
        float4 r4 = dl[idx];
        float d0 = __fmul_rn(r4.x, 0.1f);
        float d1 = __fmul_rn(r4.y, 0.1f);
        float d2 = __fmul_rn(r4.z, 0.2f);
        float d3 = __fmul_rn(r4.w, 0.2f);
        float h  = __fsub_rn(a4.z, a4.x);
        float w  = __fsub_rn(a4.w, a4.y);
        float cy = __fadd_rn(__fadd_rn(a4.x, __fmul_rn(0.5f, h)), __fmul_rn(d0, h));
        float cx = __fadd_rn(__fadd_rn(a4.y, __fmul_rn(0.5f, w)), __fmul_rn(d1, w));
        float h2 = __fmul_rn(h, expf(d2));
        float w2 = __fmul_rn(w, expf(d3));
        float y1 = __fsub_rn(cy, __fmul_rn(0.5f, h2));
        float x1 = __fsub_rn(cx, __fmul_rn(0.5f, w2));
        float y2 = __fadd_rn(y1, h2);
        float x2 = __fadd_rn(x1, w2);
        y1 = fminf(fmaxf(y1, 0.0f), 1.0f);
        x1 = fminf(fmaxf(x1, 0.0f), 1.0f);
        y2 = fminf(fmaxf(y2, 0.0f), 1.0f);
        x2 = fminf(fmaxf(x2, 0.0f), 1.0f);
        g_boxes[b * KTOP + i] = make_float4(y1, x1, y2, x2);
        g_areas[b * KTOP + i] = __fmul_rn(__fsub_rn(y2, y1), __fsub_rn(x2, x1));
    }
}

/* ------- kernel 5a: assign boxes to grid cells -------------------------- */
__global__ void cell_assign_kernel() {
    int b = blockIdx.y;
    int i = blockIdx.x * blockDim.x + threadIdx.x;
    if (i >= KTOP) return;
    float4 bx = g_boxes[b * KTOP + i];
    int cy0 = min(CELLG - 1, (int)(bx.x * CELLG));
    int cx0 = min(CELLG - 1, (int)(bx.y * CELLG));
    int cy1 = min(CELLG - 1, (int)(bx.z * CELLG));
    int cx1 = min(CELLG - 1, (int)(bx.w * CELLG));
    for (int cy = cy0; cy <= cy1; ++cy)
        for (int cx = cx0; cx <= cx1; ++cx) {
            int cell = cy * CELLG + cx;
            unsigned int pos = atomicAdd(&g_ccnt[b][cell], 1u);
            if (pos < CELLCAP) g_cells[b][cell][pos] = (unsigned int)i;
            else               g_cellovf[b] = 1u;
        }
}

/* ------- kernel 5b: per-cell pair evaluation (exact canonical dedup) ---- */
__global__ void __launch_bounds__(256)
cell_pairs_kernel() {
    int cell = blockIdx.x;
    int b    = blockIdx.y;
    int cellx = cell & (CELLG - 1);
    int celly = cell >> 4;
    __shared__ float4       sbx[CELLCAP];
    __shared__ unsigned short sid[CELLCAP];
    int n = (int)min(g_ccnt[b][cell], (unsigned int)CELLCAP);
    for (int t = threadIdx.x; t < n; t += blockDim.x) {
        unsigned int gi = g_cells[b][cell][t];
        sid[t] = (unsigned short)gi;
        sbx[t] = g_boxes[b * KTOP + gi];
    }
    __syncthreads();
    int npairs = n * (n - 1) / 2;
    for (int p = threadIdx.x; p < npairs; p += blockDim.x) {
        /* decode triangular pair index -> (a, bq), a < bq */
        float tn = 2.0f * n - 1.0f;
        int a = (int)((tn - sqrtf(tn * tn - 8.0f * (float)p)) * 0.5f);
        if (a < 0) a = 0;
        if (a > n - 2) a = n - 2;
        /* start(a) = a*n - a*(a+1)/2 ; fixup for float error */
        while (a > 0 && a * n - a * (a + 1) / 2 > p) --a;
        while ((a + 1) * n - (a + 1) * (a + 2) / 2 <= p) ++a;
        int bq = p - (a * n - a * (a + 1) / 2) + a + 1;

        float4 A = sbx[a], Bx = sbx[bq];
        float yy1 = fmaxf(A.x, Bx.x);
        float xx1 = fmaxf(A.y, Bx.y);
        float yy2 = fminf(A.z, Bx.z);
        float xx2 = fminf(A.w, Bx.w);
        float inter = __fmul_rn(fmaxf(__fsub_rn(yy2, yy1), 0.0f),
                                fmaxf(__fsub_rn(xx2, xx1), 0.0f));
        if (inter > 0.0f) {
            /* canonical cell = cell containing (yy1, xx1): dedup across cells */
            int ccy = min(CELLG - 1, (int)(yy1 * CELLG));
            int ccx = min(CELLG - 1, (int)(xx1 * CELLG));
            if (ccy == celly && ccx == cellx) {
                float aA = __fmul_rn(__fsub_rn(A.z, A.x), __fsub_rn(A.w, A.y));
                float aB = __fmul_rn(__fsub_rn(Bx.z, Bx.x), __fsub_rn(Bx.w, Bx.y));
                float uni = __fsub_rn(__fadd_rn(aA, aB), inter);
                if (uni > 0.0f && !(__fdiv_rn(inter, uni) <= 0.7f)) {
                    int ia = (int)sid[a], ib = (int)sid[bq];
                    int i = min(ia, ib), j = max(ia, ib);
                    unsigned int pos = atomicAdd(&g_pcnt[b][i], 1u);
                    if (pos < SLOTS) {
                        g_padj[b][i][pos] = (unsigned int)j;
                    } else {
                        unsigned int sp2 = atomicAdd(&g_spillcnt[b], 1u);
                        if (sp2 < SPILLCAP)
                            g_spill[b][sp2] =
                                ((unsigned int)i << 16) | (unsigned int)j;
                    }
                }
            }
        }
    }
}

/* ------- kernel 5c: brute-force fallback (only if a cell overflowed) ---- */
#define MBK_THREADS 256
#define MBK_RPW     8
#define MBK_ROWS    (8 * MBK_RPW)
#define MBK_CHUNK   2048

__global__ void __launch_bounds__(MBK_THREADS)
pair_fallback_kernel() {
    int b = blockIdx.y;
    if (!g_cellovf[b]) return;                  /* common case: exit */
    int rowbase = blockIdx.x * MBK_ROWS;
    int warp    = threadIdx.x >> 5;
    int lane    = threadIdx.x & 31;
    int i0      = rowbase + warp * MBK_RPW;

    __shared__ float4 sbox[MBK_CHUNK];
    const float4* boxes = g_boxes + b * KTOP;
    const float*  areas = g_areas + b * KTOP;

    float4 rb[MBK_RPW]; float ra[MBK_RPW];
#pragma unroll
    for (int r = 0; r < MBK_RPW; ++r) {
        int i = i0 + r;
        if (i < KTOP) { rb[r] = boxes[i]; ra[r] = areas[i]; }
        else { rb[r] = make_float4(0.f, 0.f, 0.f, 0.f); ra[r] = 0.f; }
    }
    for (int chunk = 0; chunk < KTOP; chunk += MBK_CHUNK) {
        int cn = min(MBK_CHUNK, KTOP - chunk);
        __syncthreads();
        for (int t = threadIdx.x; t < cn; t += MBK_THREADS)
            sbox[t] = boxes[chunk + t];
        __syncthreads();
        if (chunk + cn <= rowbase) continue;
        int wstart = (i0 + 1 > chunk) ? ((i0 + 1 - chunk) >> 5) : 0;
        int wend   = (cn + 31) >> 5;
        for (int wd = wstart; wd < wend; ++wd) {
            int j = chunk + wd * 32 + lane;
            float4 cbx = sbox[wd * 32 + lane];
            float cax = __fmul_rn(__fsub_rn(cbx.z, cbx.x),
                                  __fsub_rn(cbx.w, cbx.y));
            bool jok = (j < KTOP);
            unsigned int supmask = 0;
#pragma unroll
            for (int r = 0; r < MBK_RPW; ++r) {
                float yy1 = fmaxf(rb[r].x, cbx.x);
                float xx1 = fmaxf(rb[r].y, cbx.y);
                float yy2 = fminf(rb[r].z, cbx.z);
                float xx2 = fminf(rb[r].w, cbx.w);
                float inter = __fmul_rn(fmaxf(__fsub_rn(yy2, yy1), 0.0f),
                                        fmaxf(__fsub_rn(xx2, xx1), 0.0f));
                bool sup = false;
                if (inter > 0.0f && jok && j > i0 + r) {
                    float uni = __fsub_rn(__fadd_rn(ra[r], cax), inter);
                    if (uni > 0.0f)
                        sup = !(__fdiv_rn(inter, uni) <= 0.7f);
                }
                supmask |= sup ? (1u << r) : 0u;
            }
            if (__any_sync(0xFFFFFFFFu, supmask != 0u)) {
                while (supmask) {
                    int r = __ffs(supmask) - 1;
                    supmask &= supmask - 1u;
                    int i = i0 + r;
                    unsigned int pos = atomicAdd(&g_pcnt[b][i], 1u);
                    if (pos < SLOTS) {
                        g_padj[b][i][pos] = (unsigned int)j;
                    } else {
                        unsigned int sp2 = atomicAdd(&g_spillcnt[b], 1u);
                        if (sp2 < SPILLCAP)
                            g_spill[b][sp2] =
                                ((unsigned int)i << 16) | (unsigned int)j;
                    }
                }
            }
        }
    }
}

/* ------- kernel 6: sparse serial greedy pass ---------------------------- */
__global__ void __launch_bounds__(32, 1)
nms_serial_kernel(float* __restrict__ out) {
    int b    = blockIdx.x;
    int lane = threadIdx.x;
    __shared__ unsigned long long sbm[94];
    __shared__ unsigned long long szero[94];
    __shared__ unsigned char      scnt[KTOP];
    __shared__ int                s_picks[PROP];
    __shared__ int                s_ctl[2];

    const float* areas = g_areas + b * KTOP;

    for (int wu = lane; wu < 94; wu += 32)
        sbm[wu] = (wu < 93) ? ~0ull : ((1ull << 48) - 1ull);

    for (int wu = 0; wu < 94; ++wu) {
        int i1 = wu * 64 + lane;
        int i2 = i1 + 32;
        bool z1 = (i1 < KTOP) && (areas[i1] == 0.0f);
        bool z2 = (i2 < KTOP) && (areas[i2] == 0.0f);
        unsigned int lo = __ballot_sync(0xFFFFFFFFu, z1);
        unsigned int hi = __ballot_sync(0xFFFFFFFFu, z2);
        if (lane == 0)
            szero[wu] = ((unsigned long long)hi << 32) | lo;
    }

    for (int i = lane; i < KTOP; i += 32) {
        unsigned int c = g_pcnt[b][i];
        scnt[i] = (unsigned char)(c > 255u ? 255u : c);
    }
    __syncwarp();

    if (lane == 0) {
        int cur = 0, sp = 0, fill = -1;
        int sc = (int)g_spillcnt[b];
        if (sc > SPILLCAP) sc = SPILLCAP;
        while (sp < PROP) {
            int wu = cur >> 6;
            unsigned long long w =
                (wu < 94) ? (sbm[wu] & (~0ull << (cur & 63))) : 0ull;
            while (!w) {
                if (++wu >= 94) break;
                w = sbm[wu];
            }
            if (wu >= 94) break;
            int i = (wu << 6) + (__ffsll((long long)w) - 1);
            s_picks[sp++] = i;
            if ((szero[wu] >> (i & 63)) & 1ull) {
                fill = i;
                break;
            }
            cur = i + 1;
            int n = scnt[i];
            if (n) {
                const unsigned int* adj = g_padj[b][i];
                int mslots = n < SLOTS ? n : SLOTS;
                for (int t = 0; t < mslots; ++t) {
                    int j = (int)adj[t];
                    sbm[j >> 6] &= ~(1ull << (j & 63));
                }
                if (n > SLOTS) {
                    for (int k = 0; k < sc; ++k) {
                        unsigned int p = g_spill[b][k];
                        if ((int)(p >> 16) == i) {
                            int j = (int)(p & 0xFFFFu);
                            sbm[j >> 6] &= ~(1ull << (j & 63));
                        }
                    }
                }
            }
        }
        s_ctl[0] = sp;
        s_ctl[1] = fill;
    }
    __syncwarp();
    int step = s_ctl[0];
    int fill = s_ctl[1];

    for (int s2 = step + lane; s2 < PROP; s2 += 32) s_picks[s2] = fill;
    __syncwarp();
    const float4* boxes = g_boxes + b * KTOP;
    float4* o = (float4*)out + b * PROP;
    for (int s2 = lane; s2 < PROP; s2 += 32) {
        int p = s_picks[s2];
        o[s2] = (p >= 0) ? boxes[p] : make_float4(0.f, 0.f, 0.f, 0.f);
    }
}

/* ---------------- launch ------------------------------------------------ */
extern "C" void kernel_launch(void* const* d_in, const int* in_sizes, int n_in,
                              void* d_out, int out_size) {
    const float* probs   = (const float*)d_in[0];  /* (B, A, 2) */
    const float* bbox    = (const float*)d_in[1];  /* (B, A, 4) */
    const float* anchors = (const float*)d_in[2];  /* (B, A, 4) */
    float* out = (float*)d_out;                    /* (B, 1000, 4) */

    cudaFuncSetAttribute(sort_gather_kernel,
                         cudaFuncAttributeMaxDynamicSharedMemorySize, SORTN * 8);

    clear_kernel<<<1024, 256>>>();
    dim3 hg(256, BATCH);
    hist_kernel<<<hg, 256>>>(probs);
    findthresh_kernel<<<BATCH, 256>>>();
    compact_kernel<<<hg, 256>>>(probs);
    sort_gather_kernel<<<BATCH, 1024, SORTN * 8>>>(bbox, anchors);
    dim3 ag((KTOP + 255) / 256, BATCH);
    cell_assign_kernel<<<ag, 256>>>();
    dim3 cg(NCELL, BATCH);
    cell_pairs_kernel<<<cg, 256>>>();
    dim3 fg((KTOP + MBK_ROWS - 1) / MBK_ROWS, BATCH);
    pair_fallback_kernel<<<fg, MBK_THREADS>>>();
    nms_serial_kernel<<<BATCH, 32>>>(out);
}